// round 3
// baseline (speedup 1.0000x reference)
#include <cuda_runtime.h>

// Problem constants
#define FEAT      16
#define BATCH     4
#define GHW       512
#define NPIX      (BATCH * GHW * GHW)        // 1,048,576 pixels
#define PIX_PER_B (GHW * GHW)                // 262,144

// Texture sizes
#define W1 1024
#define W2 512
#define W3 256
#define W4 128
#define N1 (W1 * W1)   // 1,048,576
#define N2 (W2 * W2)   // 262,144
#define N3 (W3 * W3)   // 65,536
#define N4 (W4 * W4)   // 16,384

// Offsets into transposed scratch (in floats); layout (H, W, F)
#define O1 0
#define O2 (O1 + N1 * FEAT)   // 16,777,216
#define O3 (O2 + N2 * FEAT)   // 20,971,520
#define O4 (O3 + N3 * FEAT)   // 22,020,096
#define TOTAL_TEX (O4 + N4 * FEAT)  // 22,282,240 floats (~85 MB)

// Device scratch for (H, W, F)-layout textures. Static __device__ array:
// allowed under the allocation guards.
static __device__ float g_tex[TOTAL_TEX];

// ---------------------------------------------------------------------------
// Pass 1: transpose (F, H, W) -> (H, W, F).
// One thread per (y, x) position. Reads are coalesced per-feature (lanes span
// consecutive x); writes are 4x STG.128 of 64 contiguous bytes per thread.
// ---------------------------------------------------------------------------
__global__ void transpose_kernel(const float* __restrict__ src, int off, int n)
{
    int idx = blockIdx.x * blockDim.x + threadIdx.x;
    if (idx >= n) return;
    float vals[FEAT];
#pragma unroll
    for (int f = 0; f < FEAT; ++f)
        vals[f] = __ldg(src + (size_t)f * n + idx);
    float4* d = reinterpret_cast<float4*>(g_tex + off + (size_t)idx * FEAT);
#pragma unroll
    for (int j = 0; j < 4; ++j)
        d[j] = make_float4(vals[4*j], vals[4*j+1], vals[4*j+2], vals[4*j+3]);
}

// ---------------------------------------------------------------------------
// Pass 2: bilinear sample, 4 mip levels summed.
// Lane mapping: tid = pixel*16 + feature. A half-warp (16 lanes) shares one
// pixel, so each corner load is a coalesced 64B access (2 L1 wavefronts per
// warp-instruction instead of 32 for divergent gathers).
// ---------------------------------------------------------------------------
__device__ __forceinline__ float sample_one(const float* __restrict__ t,
                                            int S, float ux, float uy, int f)
{
    // align_corners=False unnormalize + border clamp
    float ix = fminf(fmaxf(ux * (float)S - 0.5f, 0.0f), (float)(S - 1));
    float iy = fminf(fmaxf(uy * (float)S - 0.5f, 0.0f), (float)(S - 1));
    float x0f = floorf(ix);
    float y0f = floorf(iy);
    float wx = ix - x0f;
    float wy = iy - y0f;
    int x0 = (int)x0f;
    int y0 = (int)y0f;
    int x1 = min(x0 + 1, S - 1);
    int y1 = min(y0 + 1, S - 1);

    const float* r0 = t + (((size_t)y0 * S) << 4);
    const float* r1 = t + (((size_t)y1 * S) << 4);
    float v00 = __ldg(r0 + (x0 << 4) + f);
    float v01 = __ldg(r0 + (x1 << 4) + f);
    float v10 = __ldg(r1 + (x0 << 4) + f);
    float v11 = __ldg(r1 + (x1 << 4) + f);

    float top = v00 + (v01 - v00) * wx;
    float bot = v10 + (v11 - v10) * wx;
    return top + (bot - top) * wy;
}

__global__ void __launch_bounds__(256) sample_kernel(const float2* __restrict__ grid,
                                                     float* __restrict__ out)
{
    int tid = blockIdx.x * blockDim.x + threadIdx.x;   // NPIX*16 threads
    int f   = tid & 15;
    int pix = tid >> 4;

    float2 g = __ldg(&grid[pix]);      // 16 lanes share address -> broadcast
    float ux = (g.x + 1.0f) * 0.5f;
    float uy = (g.y + 1.0f) * 0.5f;

    float acc;
    acc  = sample_one(g_tex + O1, W1, ux, uy, f);
    acc += sample_one(g_tex + O2, W2, ux, uy, f);
    acc += sample_one(g_tex + O3, W3, ux, uy, f);
    acc += sample_one(g_tex + O4, W4, ux, uy, f);

    int b  = pix >> 18;                 // pix / 262144
    int hw = pix & (PIX_PER_B - 1);
    out[(((b << 4) + f) << 18) + hw] = acc;
}

extern "C" void kernel_launch(void* const* d_in, const int* in_sizes, int n_in,
                              void* d_out, int out_size)
{
    const float* x  = (const float*)d_in[0];   // (B, 512, 512, 2)
    const float* t1 = (const float*)d_in[1];   // (16, 1024, 1024)
    const float* t2 = (const float*)d_in[2];   // (16, 512, 512)
    const float* t3 = (const float*)d_in[3];   // (16, 256, 256)
    const float* t4 = (const float*)d_in[4];   // (16, 128, 128)
    float* out = (float*)d_out;

    transpose_kernel<<<(N1 + 255) / 256, 256>>>(t1, O1, N1);
    transpose_kernel<<<(N2 + 255) / 256, 256>>>(t2, O2, N2);
    transpose_kernel<<<(N3 + 255) / 256, 256>>>(t3, O3, N3);
    transpose_kernel<<<(N4 + 255) / 256, 256>>>(t4, O4, N4);

    int total = NPIX * FEAT;           // 16,777,216 threads
    sample_kernel<<<total / 256, 256>>>((const float2*)x, out);
}

// round 4
// speedup vs baseline: 1.5204x; 1.5204x over previous
#include <cuda_runtime.h>

// Problem constants
#define FEAT      16
#define BATCH     4
#define GHW       512
#define NPIX      (BATCH * GHW * GHW)        // 1,048,576 pixels
#define PIX_PER_B (GHW * GHW)                // 262,144

// Texture sizes
#define W1 1024
#define W2 512
#define W3 256
#define W4 128
#define N1 (W1 * W1)   // 1,048,576
#define N2 (W2 * W2)   // 262,144
#define N3 (W3 * W3)   // 65,536
#define N4 (W4 * W4)   // 16,384
#define NTOT (N1 + N2 + N3 + N4)   // 1,392,640

// Offsets into transposed scratch (in floats); layout (H, W, F)
#define O1 0
#define O2 (O1 + N1 * FEAT)   // 16,777,216
#define O3 (O2 + N2 * FEAT)   // 20,971,520
#define O4 (O3 + N3 * FEAT)   // 22,020,096
#define TOTAL_TEX (O4 + N4 * FEAT)  // 22,282,240 floats (~85 MB)

// Device scratch for (H, W, F)-layout textures.
static __device__ float g_tex[TOTAL_TEX];

// ---------------------------------------------------------------------------
// Pass 1 (single launch): transpose all 4 levels (F, H, W) -> (H, W, F).
// Reads are coalesced per-feature; writes are 4x STG.128, 64B contiguous.
// ---------------------------------------------------------------------------
__global__ void transpose_all_kernel(const float* __restrict__ t1,
                                     const float* __restrict__ t2,
                                     const float* __restrict__ t3,
                                     const float* __restrict__ t4)
{
    int gidx = blockIdx.x * blockDim.x + threadIdx.x;
    const float* src;
    int idx, n, off;
    if (gidx < N1)                { src = t1; idx = gidx;                 n = N1; off = O1; }
    else if (gidx < N1 + N2)      { src = t2; idx = gidx - N1;            n = N2; off = O2; }
    else if (gidx < N1 + N2 + N3) { src = t3; idx = gidx - (N1 + N2);     n = N3; off = O3; }
    else if (gidx < NTOT)         { src = t4; idx = gidx - (N1 + N2 + N3);n = N4; off = O4; }
    else return;

    float vals[FEAT];
#pragma unroll
    for (int f = 0; f < FEAT; ++f)
        vals[f] = __ldg(src + (size_t)f * n + idx);
    float4* d = reinterpret_cast<float4*>(g_tex + off + (size_t)idx * FEAT);
#pragma unroll
    for (int j = 0; j < 4; ++j)
        d[j] = make_float4(vals[4*j], vals[4*j+1], vals[4*j+2], vals[4*j+3]);
}

// ---------------------------------------------------------------------------
// Pass 2: bilinear sample, 4 mip levels summed.
// Lane mapping: tid = pixel*16 + feature (half-warp shares a pixel, so each
// corner load is a coalesced 64B access). Output is staged through SMEM so
// each warp emits one fully-coalesced 128B streaming store per feature row.
// ---------------------------------------------------------------------------
__device__ __forceinline__ float sample_one(const float* __restrict__ t,
                                            int S, float ux, float uy, int f)
{
    // align_corners=False unnormalize + border clamp
    float ix = fminf(fmaxf(ux * (float)S - 0.5f, 0.0f), (float)(S - 1));
    float iy = fminf(fmaxf(uy * (float)S - 0.5f, 0.0f), (float)(S - 1));
    float x0f = floorf(ix);
    float y0f = floorf(iy);
    float wx = ix - x0f;
    float wy = iy - y0f;
    int x0 = (int)x0f;
    int y0 = (int)y0f;
    int x1 = min(x0 + 1, S - 1);
    int y1 = min(y0 + 1, S - 1);

    const float* r0 = t + (((size_t)y0 * S) << 4);
    const float* r1 = t + (((size_t)y1 * S) << 4);
    float v00 = __ldg(r0 + (x0 << 4) + f);
    float v01 = __ldg(r0 + (x1 << 4) + f);
    float v10 = __ldg(r1 + (x0 << 4) + f);
    float v11 = __ldg(r1 + (x1 << 4) + f);

    float top = v00 + (v01 - v00) * wx;
    float bot = v10 + (v11 - v10) * wx;
    return top + (bot - top) * wy;
}

#define SAMP_THREADS 512            // 32 pixels x 16 features per block

__global__ void __launch_bounds__(SAMP_THREADS) sample_kernel(
    const float2* __restrict__ grid, float* __restrict__ out)
{
    __shared__ float stage[32 * 17];       // [pix_local][feat], padded

    int tid  = threadIdx.x;
    int f    = tid & 15;
    int pl   = tid >> 4;                   // local pixel 0..31
    int pix0 = blockIdx.x * 32;            // first pixel of this block
    int pix  = pix0 + pl;

    float2 g = __ldg(&grid[pix]);          // 16 lanes share address -> broadcast
    float ux = (g.x + 1.0f) * 0.5f;
    float uy = (g.y + 1.0f) * 0.5f;

    float acc;
    acc  = sample_one(g_tex + O1, W1, ux, uy, f);
    acc += sample_one(g_tex + O2, W2, ux, uy, f);
    acc += sample_one(g_tex + O3, W3, ux, uy, f);
    acc += sample_one(g_tex + O4, W4, ux, uy, f);

    stage[pl * 17 + f] = acc;
    __syncthreads();

    // Warp w handles feature w; lane l handles local pixel l.
    int w = tid >> 5;                      // 0..15 = feature
    int l = tid & 31;                      // 0..31 = local pixel
    float v = stage[l * 17 + w];

    int gp = pix0 + l;                     // 32 consecutive pixels, same batch
    int b  = gp >> 18;                     // gp / 262144
    int hw = gp & (PIX_PER_B - 1);
    // out layout (B, F, 512, 512): fully coalesced 128B per warp, streaming
    __stcs(&out[(((size_t)(b << 4) + w) << 18) + hw], v);
}

extern "C" void kernel_launch(void* const* d_in, const int* in_sizes, int n_in,
                              void* d_out, int out_size)
{
    const float* x  = (const float*)d_in[0];   // (B, 512, 512, 2)
    const float* t1 = (const float*)d_in[1];   // (16, 1024, 1024)
    const float* t2 = (const float*)d_in[2];   // (16, 512, 512)
    const float* t3 = (const float*)d_in[3];   // (16, 256, 256)
    const float* t4 = (const float*)d_in[4];   // (16, 128, 128)
    float* out = (float*)d_out;

    transpose_all_kernel<<<(NTOT + 255) / 256, 256>>>(t1, t2, t3, t4);

    sample_kernel<<<NPIX / 32, SAMP_THREADS>>>((const float2*)x, out);
}

// round 6
// speedup vs baseline: 2.3136x; 1.5217x over previous
#include <cuda_runtime.h>

// Problem constants
#define FEAT      16
#define BATCH     4
#define GHW       512
#define NPIX      (BATCH * GHW * GHW)        // 1,048,576 pixels
#define PIX_PER_B (GHW * GHW)                // 262,144

// Texture sizes
#define W1 1024
#define W2 512
#define W3 256
#define W4 128
#define N1 (W1 * W1)
#define N2 (W2 * W2)
#define N3 (W3 * W3)
#define N4 (W4 * W4)
#define NTOT (N1 + N2 + N3 + N4)   // 1,392,640

// Offsets into transposed scratch (in floats); layout (H, W, F)
#define O1 0
#define O2 (O1 + N1 * FEAT)
#define O3 (O2 + N2 * FEAT)
#define O4 (O3 + N3 * FEAT)
#define TOTAL_TEX (O4 + N4 * FEAT)  // 22,282,240 floats (~85 MB)

static __device__ float g_tex[TOTAL_TEX];

// ---------------------------------------------------------------------------
// Pass 1: transpose all 4 levels (F, H, W) -> (H, W, F). Single launch.
// ---------------------------------------------------------------------------
__global__ void transpose_all_kernel(const float* __restrict__ t1,
                                     const float* __restrict__ t2,
                                     const float* __restrict__ t3,
                                     const float* __restrict__ t4)
{
    int gidx = blockIdx.x * blockDim.x + threadIdx.x;
    const float* src;
    int idx, n, off;
    if (gidx < N1)                { src = t1; idx = gidx;                  n = N1; off = O1; }
    else if (gidx < N1 + N2)      { src = t2; idx = gidx - N1;             n = N2; off = O2; }
    else if (gidx < N1 + N2 + N3) { src = t3; idx = gidx - (N1 + N2);      n = N3; off = O3; }
    else if (gidx < NTOT)         { src = t4; idx = gidx - (N1 + N2 + N3); n = N4; off = O4; }
    else return;

    float vals[FEAT];
#pragma unroll
    for (int f = 0; f < FEAT; ++f)
        vals[f] = __ldg(src + (size_t)f * n + idx);
    float4* d = reinterpret_cast<float4*>(g_tex + off + (size_t)idx * FEAT);
#pragma unroll
    for (int j = 0; j < 4; ++j)
        d[j] = make_float4(vals[4*j], vals[4*j+1], vals[4*j+2], vals[4*j+3]);
}

// ---------------------------------------------------------------------------
// Pass 2: bilinear sample, 4 mip levels summed.
// tid = pixel*4 + fq; each thread handles 4 features (one float4 per corner).
// Coordinate math replicated only 4x per pixel; corner loads are LDG.128.
// ---------------------------------------------------------------------------
__device__ __forceinline__ void sample_level(const float* __restrict__ t,
                                             int S, float ux, float uy,
                                             int fq, float4& acc)
{
    float ix = fminf(fmaxf(fmaf(ux, (float)S, -0.5f), 0.0f), (float)(S - 1));
    float iy = fminf(fmaxf(fmaf(uy, (float)S, -0.5f), 0.0f), (float)(S - 1));
    float x0f = floorf(ix);
    float y0f = floorf(iy);
    float wx = ix - x0f;
    float wy = iy - y0f;
    int x0 = (int)x0f;
    int y0 = (int)y0f;
    int x1 = min(x0 + 1, S - 1);
    int y1 = min(y0 + 1, S - 1);

    const float4* base = reinterpret_cast<const float4*>(t);
    // float4 index: (y*S + x)*4 + fq
    int r0 = y0 * S;
    int r1 = y1 * S;
    float4 v00 = __ldg(base + ((r0 + x0) << 2) + fq);
    float4 v01 = __ldg(base + ((r0 + x1) << 2) + fq);
    float4 v10 = __ldg(base + ((r1 + x0) << 2) + fq);
    float4 v11 = __ldg(base + ((r1 + x1) << 2) + fq);

    float w00 = (1.0f - wx) * (1.0f - wy);
    float w01 = wx * (1.0f - wy);
    float w10 = (1.0f - wx) * wy;
    float w11 = wx * wy;

    acc.x = fmaf(v00.x, w00, fmaf(v01.x, w01, fmaf(v10.x, w10, fmaf(v11.x, w11, acc.x))));
    acc.y = fmaf(v00.y, w00, fmaf(v01.y, w01, fmaf(v10.y, w10, fmaf(v11.y, w11, acc.y))));
    acc.z = fmaf(v00.z, w00, fmaf(v01.z, w01, fmaf(v10.z, w10, fmaf(v11.z, w11, acc.z))));
    acc.w = fmaf(v00.w, w00, fmaf(v01.w, w01, fmaf(v10.w, w10, fmaf(v11.w, w11, acc.w))));
}

#define SAMP_THREADS 256            // 64 pixels x 4 feature-quads per block

__global__ void __launch_bounds__(SAMP_THREADS) sample_kernel(
    const float2* __restrict__ grid, float* __restrict__ out)
{
    int tid = blockIdx.x * SAMP_THREADS + threadIdx.x;
    int fq  = tid & 3;                  // feature quad 0..3
    int pix = tid >> 2;

    float2 g = __ldg(&grid[pix]);       // 4 lanes share address -> broadcast
    float ux = fmaf(g.x, 0.5f, 0.5f);
    float uy = fmaf(g.y, 0.5f, 0.5f);

    float4 acc = make_float4(0.f, 0.f, 0.f, 0.f);
    sample_level(g_tex + O1, W1, ux, uy, fq, acc);
    sample_level(g_tex + O2, W2, ux, uy, fq, acc);
    sample_level(g_tex + O3, W3, ux, uy, fq, acc);
    sample_level(g_tex + O4, W4, ux, uy, fq, acc);

    // out layout (B, F, 512, 512). Each warp's store j covers 4 clusters of
    // 8 consecutive pixels = 4 full 32B sectors -> no write amplification.
    int b  = pix >> 18;
    int hw = pix & (PIX_PER_B - 1);
    float* o = out + (((size_t)(b << 4) + (fq << 2)) << 18) + hw;
    __stcs(o,                     acc.x);
    __stcs(o + PIX_PER_B,         acc.y);
    __stcs(o + 2 * PIX_PER_B,     acc.z);
    __stcs(o + 3 * PIX_PER_B,     acc.w);
}

extern "C" void kernel_launch(void* const* d_in, const int* in_sizes, int n_in,
                              void* d_out, int out_size)
{
    const float* x  = (const float*)d_in[0];   // (B, 512, 512, 2)
    const float* t1 = (const float*)d_in[1];
    const float* t2 = (const float*)d_in[2];
    const float* t3 = (const float*)d_in[3];
    const float* t4 = (const float*)d_in[4];
    float* out = (float*)d_out;

    transpose_all_kernel<<<(NTOT + 255) / 256, 256>>>(t1, t2, t3, t4);

    sample_kernel<<<(NPIX * 4) / SAMP_THREADS, SAMP_THREADS>>>(
        (const float2*)x, out);
}